// round 13
// baseline (speedup 1.0000x reference)
#include <cuda_runtime.h>
#include <cstdint>

// SurfEval: NURBS surface evaluation. B=8, M=N=64, P=Q=3, GRID=512, DIM=3.
//
// R13: single-g tiles to double the block count (grid-capped occupancy was the
// binder: 1024 blocks = 27.7 warps/SM). Now 4096 tiles, TPB=2 -> 2048 blocks,
// slim smem (17KB) and <=56 regs -> 9 CTAs/SM = 36 warps/SM. Pipeline per
// block unchanged: cp.async prefetch of the 4-row ctrl window, Stage A (LDS),
// Stage B -> staging, cp.async.bulk store drains behind the next tile.

#define GRID_N 512
#define MCTRL 64
#define NCTRL 64
#define ROWF4 (GRID_N * 3 / 4)     // 384 float4 per (b,g) output row
#define TILES_PER_BLOCK 2
#define CWIN (4 * 64)              // 4 ctrl rows x 64 float4 = 4KB window

__device__ __forceinline__ void prefetch_ctrl(const float4* __restrict__ ctrl,
                                              const int* __restrict__ uspan,
                                              int tile, float4* cbuf, int t)
{
    const int g  = tile & (GRID_N - 1);
    const int b  = tile >> 9;
    const int us = __ldg(uspan + g);
    const float4* src0 = ctrl + (b * MCTRL + (us - 3)) * NCTRL;  // rows us-3..us, always in-range
#pragma unroll
    for (int i = t; i < CWIN; i += 128) {
        const uint32_t dst = (uint32_t)__cvta_generic_to_shared(cbuf + i);
        asm volatile("cp.async.cg.shared.global [%0], [%1], 16;"
                     :: "r"(dst), "l"(src0 + i) : "memory");
    }
    asm volatile("cp.async.commit_group;" ::: "memory");
}

__global__ __launch_bounds__(128, 9) void surf_eval_kernel(
    const float4* __restrict__ ctrl,   // (B, 64, 64) float4
    const int*    __restrict__ uspan,  // (512)
    const int4*   __restrict__ vspan4, // (512) ints viewed as (128) int4
    const float4* __restrict__ Nu,     // (512) float4
    const float4* __restrict__ Nv,     // (512) float4
    float4*       __restrict__ out,    // (B*512*512*3)/4 float4
    int n_blocks)                      // gridDim.x (tiles = 2*n_blocks)
{
    __shared__ float4 Su[NCTRL + 1];         // +1 zero guard at n=64
    __shared__ float4 obuf[2][ROWF4];        // [parity][row], 6144B each
    __shared__ float4 cbuf[CWIN];            // prefetched 4-row ctrl window

    const int t = threadIdx.x;

    // ---- prologue: prefetch tile 0's ctrl window ----
    prefetch_ctrl(ctrl, uspan, blockIdx.x, cbuf, t);

    // ---- per-block (tile-invariant) Stage-B setup: weights + window base ----
    const int4 vsv = __ldg(vspan4 + t);
    const int  j0  = vsv.x - 3;
    float w[4][5];
    {
        const int h0 = t << 2;
        const int vd[4] = {0, vsv.y - vsv.x, vsv.z - vsv.x, vsv.w - vsv.x};
#pragma unroll
        for (int k = 0; k < 4; ++k) {
            const float4 nv = __ldg(Nv + h0 + k);
            const bool s = (vd[k] != 0);           // span delta 0 or 1
            w[k][0] = s ? 0.0f : nv.x;
            w[k][1] = s ? nv.x : nv.y;
            w[k][2] = s ? nv.y : nv.z;
            w[k][3] = s ? nv.z : nv.w;
            w[k][4] = s ? nv.w : 0.0f;
        }
    }

#pragma unroll
    for (int it = 0; it < TILES_PER_BLOCK; ++it) {
        const int tile = blockIdx.x + it * n_blocks;   // 0 .. 2*n_blocks-1
        const int g    = tile & (GRID_N - 1);
        const int b    = tile >> 9;

        // ---- wait for this tile's ctrl window ----
        asm volatile("cp.async.wait_group 0;" ::: "memory");
        __syncthreads();

        // ---- Stage A (pure LDS): Su[n] = sum_r Nu[g,r] * cbuf[r][n] ----
        if (t < NCTRL) {
            const float4 nu = __ldg(Nu + g);
            const float4 c0 = cbuf[t];
            const float4 c1 = cbuf[64 + t];
            const float4 c2 = cbuf[128 + t];
            const float4 c3 = cbuf[192 + t];
            float4 a;
            a.x = nu.x * c0.x + nu.y * c1.x + nu.z * c2.x + nu.w * c3.x;
            a.y = nu.x * c0.y + nu.y * c1.y + nu.z * c2.y + nu.w * c3.y;
            a.z = nu.x * c0.z + nu.y * c1.z + nu.z * c2.z + nu.w * c3.z;
            a.w = nu.x * c0.w + nu.y * c1.w + nu.z * c2.w + nu.w * c3.w;
            Su[t] = a;
        } else if (t == NCTRL) {
            Su[NCTRL] = make_float4(0.f, 0.f, 0.f, 0.f);
        }
        __syncthreads();   // Su ready; cbuf fully consumed

        // ---- prefetch NEXT tile's ctrl window (drains behind Stage B + store) ----
        if (it + 1 < TILES_PER_BLOCK)
            prefetch_ctrl(ctrl, uspan, blockIdx.x + (it + 1) * n_blocks, cbuf, t);

        // ---- Stage B -> staging buffer (parity it&1) ----
        {
            const float4 q0 = Su[j0];
            const float4 q1 = Su[j0 + 1];
            const float4 q2 = Su[j0 + 2];
            const float4 q3 = Su[j0 + 3];
            const float4 q4 = Su[j0 + 4];

            float r[12];
#pragma unroll
            for (int k = 0; k < 4; ++k) {
                const float X = w[k][0] * q0.x + w[k][1] * q1.x + w[k][2] * q2.x + w[k][3] * q3.x + w[k][4] * q4.x;
                const float Y = w[k][0] * q0.y + w[k][1] * q1.y + w[k][2] * q2.y + w[k][3] * q3.y + w[k][4] * q4.y;
                const float Z = w[k][0] * q0.z + w[k][1] * q1.z + w[k][2] * q2.z + w[k][3] * q3.z + w[k][4] * q4.z;
                const float W = w[k][0] * q0.w + w[k][1] * q1.w + w[k][2] * q2.w + w[k][3] * q3.w + w[k][4] * q4.w;
                const float inv = __fdividef(1.0f, W);
                r[k * 3 + 0] = X * inv;
                r[k * 3 + 1] = Y * inv;
                r[k * 3 + 2] = Z * inv;
            }
            float4* ob = obuf[it & 1] + t * 3;
            ob[0] = make_float4(r[0], r[1], r[2], r[3]);
            ob[1] = make_float4(r[4], r[5], r[6], r[7]);
            ob[2] = make_float4(r[8], r[9], r[10], r[11]);
        }
        __syncthreads();   // obuf complete

        // ---- one 6144B bulk store for the row (async drain) ----
        if (t == 0) {
            asm volatile("fence.proxy.async.shared::cta;" ::: "memory");
            float4* gdst = out + (size_t)(b * GRID_N + g) * ROWF4;
            const uint32_t s = (uint32_t)__cvta_generic_to_shared(&obuf[it & 1][0]);
            asm volatile("cp.async.bulk.global.shared::cta.bulk_group [%0], [%1], %2;"
                         :: "l"(gdst), "r"(s), "r"(ROWF4 * 16) : "memory");
            asm volatile("cp.async.bulk.commit_group;" ::: "memory");
        }
    }

    // drain outstanding bulk stores before the CTA (and its smem) retires
    if (t == 0) {
        asm volatile("cp.async.bulk.wait_group 0;" ::: "memory");
    }
}

extern "C" void kernel_launch(void* const* d_in, const int* in_sizes, int n_in,
                              void* d_out, int out_size) {
    const float4* ctrl   = (const float4*)d_in[0];
    const int*    uspan  = (const int*)d_in[1];
    const int4*   vspan4 = (const int4*)d_in[2];
    const float4* Nu     = (const float4*)d_in[3];
    const float4* Nv     = (const float4*)d_in[4];

    const int B = in_sizes[0] / (MCTRL * NCTRL * 4);  // ctrl_pts elements = B*64*64*4
    const int tiles = B * GRID_N;                     // 4096 for B=8
    const int n_blocks = tiles / TILES_PER_BLOCK;     // 2048

    surf_eval_kernel<<<n_blocks, 128>>>(ctrl, uspan, vspan4, Nu, Nv,
                                        (float4*)d_out, n_blocks);
}

// round 14
// speedup vs baseline: 1.2149x; 1.2149x over previous
#include <cuda_runtime.h>
#include <cstdint>

// SurfEval: NURBS surface evaluation. B=8, M=N=64, P=Q=3, GRID=512, DIM=3.
//
// R14: warp-autonomous pipelines — ZERO __syncthreads. Each warp owns its
// h-range's Su slice (<=24 entries, lane l builds Su[j_lo+l] from 4-5 direct
// LDG.128), __syncwarp, Stage B, __syncwarp, then lane 0 bulk-stores the
// warp's contiguous 1536B output slice per g-line (cp.async.bulk). Block-wide
// lockstep (the measured ~160cyc/tile overhead + skew coupling) is gone.
// Tiles = g-pairs (2048), TPB=2 -> 1024 blocks x 128 threads.

#define GRID_N 512
#define MCTRL 64
#define NCTRL 64
#define ROWF4 (GRID_N * 3 / 4)   // 384 float4 per (b,g) output row
#define TPB 2
#define SUW 24                   // per-warp Su slice capacity (max needed ~20)

__global__ __launch_bounds__(128, 8) void surf_eval_kernel(
    const float4* __restrict__ ctrl,   // (B, 64, 64) float4
    const int*    __restrict__ uspan,  // (512)
    const int4*   __restrict__ vspan4, // (512) ints viewed as (128) int4
    const float4* __restrict__ Nu,     // (512) float4
    const float4* __restrict__ Nv,     // (512) float4
    float4*       __restrict__ out,    // (B*512*512*3)/4 float4
    int n_blocks)                      // gridDim.x (tiles = TPB*n_blocks)
{
    __shared__ float4 Su[4][2][SUW];           // [warp][gg][slice]
    __shared__ float4 obuf[4][2][2][96];       // [warp][parity][gg][96 f4] = 1536B slices

    const int t   = threadIdx.x;
    const int wid = t >> 5;
    const int lid = t & 31;

    // ---- tile-invariant Stage-B setup (depends only on t) ----
    const int4 vsv = __ldg(vspan4 + t);
    const int  j0  = vsv.x - 3;
    const int  j_lo = __shfl_sync(0xffffffffu, j0, 0);       // vspan monotonic in t
    const int  cnt  = __shfl_sync(0xffffffffu, j0, 31) + 5 - j_lo;
    const int  sl   = j0 - j_lo;                              // my window base in the slice

    float w[4][5];
    {
        const int h0 = t << 2;
        const int vd[4] = {0, vsv.y - vsv.x, vsv.z - vsv.x, vsv.w - vsv.x};
#pragma unroll
        for (int k = 0; k < 4; ++k) {
            const float4 nv = __ldg(Nv + h0 + k);
            const bool s = (vd[k] != 0);           // span delta 0 or 1
            w[k][0] = s ? 0.0f : nv.x;
            w[k][1] = s ? nv.x : nv.y;
            w[k][2] = s ? nv.y : nv.z;
            w[k][3] = s ? nv.z : nv.w;
            w[k][4] = s ? nv.w : 0.0f;
        }
    }

#pragma unroll
    for (int it = 0; it < TPB; ++it) {
        const int tile = blockIdx.x + it * n_blocks;   // 0 .. TPB*n_blocks-1
        const int g0   = (tile & 255) << 1;            // g-pair base
        const int b    = tile >> 8;                    // batch

        const int us0 = __ldg(uspan + g0);
        const int us1 = __ldg(uspan + g0 + 1);

        // ---- Stage A (warp-local): lane l builds Su[j_lo+l] for both g-lines ----
        if (lid < cnt) {
            const int n = j_lo + lid;
            float4 su0 = make_float4(0.f, 0.f, 0.f, 0.f);
            float4 su1 = su0;
            if (n <= 63) {
                const float4 nu0 = __ldg(Nu + g0);
                const float4 nu1 = __ldg(Nu + g0 + 1);
                const float4* base = ctrl + (b * MCTRL + (us0 - 3)) * NCTRL + n;
                const float4 c0 = __ldg(base);
                const float4 c1 = __ldg(base + NCTRL);
                const float4 c2 = __ldg(base + 2 * NCTRL);
                const float4 c3 = __ldg(base + 3 * NCTRL);
                su0.x = nu0.x * c0.x + nu0.y * c1.x + nu0.z * c2.x + nu0.w * c3.x;
                su0.y = nu0.x * c0.y + nu0.y * c1.y + nu0.z * c2.y + nu0.w * c3.y;
                su0.z = nu0.x * c0.z + nu0.y * c1.z + nu0.z * c2.z + nu0.w * c3.z;
                su0.w = nu0.x * c0.w + nu0.y * c1.w + nu0.z * c2.w + nu0.w * c3.w;
                if (us1 == us0) {   // warp-uniform branch
                    su1.x = nu1.x * c0.x + nu1.y * c1.x + nu1.z * c2.x + nu1.w * c3.x;
                    su1.y = nu1.x * c0.y + nu1.y * c1.y + nu1.z * c2.y + nu1.w * c3.y;
                    su1.z = nu1.x * c0.z + nu1.y * c1.z + nu1.z * c2.z + nu1.w * c3.z;
                    su1.w = nu1.x * c0.w + nu1.y * c1.w + nu1.z * c2.w + nu1.w * c3.w;
                } else {            // us1 = us0+1 (us0 <= 62 here, row us0+1 in range)
                    const float4 c4 = __ldg(base + 4 * NCTRL);
                    su1.x = nu1.x * c1.x + nu1.y * c2.x + nu1.z * c3.x + nu1.w * c4.x;
                    su1.y = nu1.x * c1.y + nu1.y * c2.y + nu1.z * c3.y + nu1.w * c4.y;
                    su1.z = nu1.x * c1.z + nu1.y * c2.z + nu1.z * c3.z + nu1.w * c4.z;
                    su1.w = nu1.x * c1.w + nu1.y * c2.w + nu1.z * c3.w + nu1.w * c4.w;
                }
            }
            Su[wid][0][lid] = su0;
            Su[wid][1][lid] = su1;
        }
        __syncwarp();

        // ---- Stage B: 4 h points x 2 g-lines -> warp obuf slice ----
#pragma unroll
        for (int gg = 0; gg < 2; ++gg) {
            const float4* SuG = Su[wid][gg];
            const float4 q0 = SuG[sl];
            const float4 q1 = SuG[sl + 1];
            const float4 q2 = SuG[sl + 2];
            const float4 q3 = SuG[sl + 3];
            const float4 q4 = SuG[sl + 4];

            float r[12];
#pragma unroll
            for (int k = 0; k < 4; ++k) {
                const float X = w[k][0] * q0.x + w[k][1] * q1.x + w[k][2] * q2.x + w[k][3] * q3.x + w[k][4] * q4.x;
                const float Y = w[k][0] * q0.y + w[k][1] * q1.y + w[k][2] * q2.y + w[k][3] * q3.y + w[k][4] * q4.y;
                const float Z = w[k][0] * q0.z + w[k][1] * q1.z + w[k][2] * q2.z + w[k][3] * q3.z + w[k][4] * q4.z;
                const float W = w[k][0] * q0.w + w[k][1] * q1.w + w[k][2] * q2.w + w[k][3] * q3.w + w[k][4] * q4.w;
                const float inv = __fdividef(1.0f, W);
                r[k * 3 + 0] = X * inv;
                r[k * 3 + 1] = Y * inv;
                r[k * 3 + 2] = Z * inv;
            }
            float4* ob = &obuf[wid][it][gg][lid * 3];
            ob[0] = make_float4(r[0], r[1], r[2], r[3]);
            ob[1] = make_float4(r[4], r[5], r[6], r[7]);
            ob[2] = make_float4(r[8], r[9], r[10], r[11]);
        }
        __syncwarp();   // warp slice complete (also protects Su for next tile)

        // ---- lane 0: bulk-store the warp's two 1536B slices (async drain) ----
        if (lid == 0) {
            asm volatile("fence.proxy.async.shared::cta;" ::: "memory");
#pragma unroll
            for (int gg = 0; gg < 2; ++gg) {
                float4* gdst = out + (size_t)(b * GRID_N + g0 + gg) * ROWF4 + 96 * wid;
                const uint32_t s = (uint32_t)__cvta_generic_to_shared(&obuf[wid][it][gg][0]);
                asm volatile("cp.async.bulk.global.shared::cta.bulk_group [%0], [%1], %2;"
                             :: "l"(gdst), "r"(s), "r"(96 * 16) : "memory");
            }
            asm volatile("cp.async.bulk.commit_group;" ::: "memory");
        }
    }

    // drain this warp's outstanding bulk stores before the CTA retires
    if (lid == 0) {
        asm volatile("cp.async.bulk.wait_group 0;" ::: "memory");
    }
}

extern "C" void kernel_launch(void* const* d_in, const int* in_sizes, int n_in,
                              void* d_out, int out_size) {
    const float4* ctrl   = (const float4*)d_in[0];
    const int*    uspan  = (const int*)d_in[1];
    const int4*   vspan4 = (const int4*)d_in[2];
    const float4* Nu     = (const float4*)d_in[3];
    const float4* Nv     = (const float4*)d_in[4];

    const int B = in_sizes[0] / (MCTRL * NCTRL * 4);  // ctrl_pts elements = B*64*64*4
    const int tiles = B * (GRID_N / 2);               // 2048 for B=8
    const int n_blocks = tiles / TPB;                 // 1024

    surf_eval_kernel<<<n_blocks, 128>>>(ctrl, uspan, vspan4, Nu, Nv,
                                        (float4*)d_out, n_blocks);
}